// round 10
// baseline (speedup 1.0000x reference)
#include <cuda_runtime.h>
#include <math.h>

#define BLOCK_THREADS 128
#define DIRS_PER_THREAD 2
#define DIRS_PER_BLOCK (BLOCK_THREADS * DIRS_PER_THREAD)
#define MAX_COMP 64

__device__ float4 g_consts[MAX_COMP];

__device__ __forceinline__ float ex2a(float x) {
    float r; asm("ex2.approx.ftz.f32 %0, %1;" : "=f"(r) : "f"(x)); return r;
}

// One-time component preprocessing: run once per launch by a single block.
__global__ void vmf_precompute_kernel(const float* __restrict__ lambdas,
                                      const float* __restrict__ kappas,
                                      const float* __restrict__ thetas,
                                      const float* __restrict__ phis,
                                      int N)
{
    int t = threadIdx.x;
    if (t < N) {
        float kappa = kappas[t];
        float lam   = lambdas[t];
        float th    = thetas[t];
        float ph    = phis[t];

        float st = sinf(th), ct = cosf(th);
        float sp = sinf(ph), cp = cosf(ph);

        float k = fmaxf(kappa, 1e-8f);
        float norm = (kappa < 1e-5f)
                   ? 0.07957747154594767f                       // 1/(4pi)
                   : k * 0.15915494309189535f / (1.0f - expf(-2.0f * k));
        float c = lam * norm;                                   // > 0 always

        const float LOG2E = 1.4426950408889634f;
        float a = kappa * LOG2E;                 // fold log2(e) into kappa
        float b = log2f(c) - a;                  // fold weight into exponent
        g_consts[t] = make_float4(a * (st * cp), a * (st * sp), a * ct, b);
    }
}

__global__ void __launch_bounds__(BLOCK_THREADS, 16)
vmf_mixture_kernel(const float* __restrict__ wi,
                   float* __restrict__ out,
                   int S, int N)
{
    __shared__ float4 sC[MAX_COMP];

    int t = threadIdx.x;
    if (t < N) sC[t] = g_consts[t];              // 1 LDG.128 + STS.128
    __syncthreads();

    int base = blockIdx.x * DIRS_PER_BLOCK + t;

    int i0 = base;
    int i1 = base + BLOCK_THREADS;
    int o0 = (i0 < S) ? 3 * i0 : 0;
    int o1 = (i1 < S) ? 3 * i1 : 0;
    float x0 = wi[o0 + 0], y0 = wi[o0 + 1], z0 = wi[o0 + 2];
    float x1 = wi[o1 + 0], y1 = wi[o1 + 1], z1 = wi[o1 + 2];

    float acc0 = 0.0f, acc1 = 0.0f;

    #pragma unroll 8
    for (int n = 0; n < N; n++) {
        float4 c = sC[n];
        float a0 = fmaf(c.x, x0, fmaf(c.y, y0, fmaf(c.z, z0, c.w)));
        float a1 = fmaf(c.x, x1, fmaf(c.y, y1, fmaf(c.z, z1, c.w)));
        acc0 += ex2a(a0);
        acc1 += ex2a(a1);
    }

    if (i0 < S) out[i0] = acc0;
    if (i1 < S) out[i1] = acc1;
}

extern "C" void kernel_launch(void* const* d_in, const int* in_sizes, int n_in,
                              void* d_out, int out_size)
{
    const float* lambdas = (const float*)d_in[0];
    const float* kappas  = (const float*)d_in[1];
    const float* thetas  = (const float*)d_in[2];
    const float* phis    = (const float*)d_in[3];
    const float* wi      = (const float*)d_in[4];
    float* out = (float*)d_out;

    int N = in_sizes[0];
    int S = in_sizes[4] / 3;

    vmf_precompute_kernel<<<1, 64>>>(lambdas, kappas, thetas, phis, N);

    int blocks = (S + DIRS_PER_BLOCK - 1) / DIRS_PER_BLOCK;
    vmf_mixture_kernel<<<blocks, BLOCK_THREADS>>>(wi, out, S, N);
}